// round 1
// baseline (speedup 1.0000x reference)
#include <cuda_runtime.h>

#define BB 2
#define NN 4096
#define GG 2048
#define CO 8
#define BW 32
#define BWIDTH (2 * BW + 1)   // 65
#define MAXP 512

// Band scratch: 2 * 2 * 2048 * 65 * 4 B ~= 2.1 MB (fits L2 for the fill pass)
__device__ float g_band0[BB][GG][BWIDTH];
__device__ float g_band1n[BB][GG][BWIDTH];

// ---------------------------------------------------------------------------
// Kernel A: per (b,g) compute the banded aggregation
//   band0[off]  = sum_n w[n,g] * w[n,g+off-BW]
//   band1n[off] = (sum_n z_n w[n,g] * w[n,h]) / (band0 + 1e-8)
// Points with w[n,g] < ~1e-18 are pruned (contribution below fp32 noise and
// far below the 1e-8 normalization floor).
// ---------------------------------------------------------------------------
__global__ void band_kernel(const float* __restrict__ xz,
                            const float* __restrict__ z,
                            const float* __restrict__ x_grid,
                            const float* __restrict__ log_scale) {
    const int g = blockIdx.x;
    const int b = blockIdx.y;
    const int tid = threadIdx.x;

    const float inv = 0.5f / __expf(2.0f * log_scale[0]);   // = 50 for this problem
    const float d2max = 41.45f / inv;                        // exp(-41.45) ~ 1e-18
    const float xg = x_grid[g];

    __shared__ float s_x[MAXP], s_w[MAXP], s_zw[MAXP];
    __shared__ int s_cnt;

    // Deterministic ordered compaction by warp 0 (ascending n)
    if (tid < 32) {
        int cnt = 0;
        const float* xb = xz + b * NN;
        const float* zb = z + b * NN;
        for (int base = 0; base < NN; base += 32) {
            const int n = base + tid;
            const float x = xb[n];
            const float d = x - xg;
            const bool keep = (d * d <= d2max);
            const unsigned mask = __ballot_sync(0xFFFFFFFFu, keep);
            if (keep) {
                const int idx = cnt + __popc(mask & ((1u << tid) - 1u));
                if (idx < MAXP) {
                    const float wg = __expf(-inv * d * d);
                    s_x[idx] = x;
                    s_w[idx] = wg;
                    s_zw[idx] = zb[n] * wg;
                }
            }
            cnt += __popc(mask);
        }
        if (tid == 0) s_cnt = (cnt < MAXP) ? cnt : MAXP;
    }
    __syncthreads();

    const int cnt = s_cnt;
    if (tid < BWIDTH) {
        const int h = g + tid - BW;
        float a0 = 0.0f, a1 = 0.0f;
        if (h >= 0 && h < GG) {
            const float xh = x_grid[h];
            for (int i = 0; i < cnt; ++i) {
                const float d = s_x[i] - xh;
                const float wh = __expf(-inv * d * d);
                a0 = fmaf(s_w[i], wh, a0);
                a1 = fmaf(s_zw[i], wh, a1);
            }
        }
        g_band0[b][g][tid] = a0;
        g_band1n[b][g][tid] = a1 / (a0 + 1e-8f);
    }
}

// ---------------------------------------------------------------------------
// Kernel B: write the full (B, C_OUT, G, G) output.
//   out[b,o,g,h] = b[o] + W[0,o]*(g==h) + W[1,o]*band0 + W[2,o]*band1n
// Off-band it's a constant fill -> pure coalesced float4 stores (HBM-bound).
// ---------------------------------------------------------------------------
__global__ void out_kernel(const float* __restrict__ W,
                           const float* __restrict__ bias,
                           float* __restrict__ out) {
    const int bo = blockIdx.z;           // b * CO + o
    const int b = bo >> 3;
    const int o = bo & 7;
    const int g = blockIdx.y;

    const float W0 = W[o];
    const float W1 = W[CO + o];
    const float W2 = W[2 * CO + o];
    const float bb = bias[o];

    const float* __restrict__ bd0 = g_band0[b][g];
    const float* __restrict__ bd1 = g_band1n[b][g];

    float4* row = reinterpret_cast<float4*>(out + ((size_t)bo * GG + g) * GG);
    const int lo = g - BW;
    const int hi = g + BW;

    for (int h4 = threadIdx.x; h4 < GG / 4; h4 += blockDim.x) {
        const int h0 = h4 * 4;
        float4 v = make_float4(bb, bb, bb, bb);
        if (h0 + 3 >= lo && h0 <= hi) {
            float* vp = &v.x;
#pragma unroll
            for (int j = 0; j < 4; ++j) {
                const int h = h0 + j;
                const int off = h - lo;
                if (off >= 0 && off < BWIDTH) {
                    float val = bb + W1 * bd0[off] + W2 * bd1[off];
                    if (h == g) val += W0;
                    vp[j] = val;
                }
            }
        }
        row[h4] = v;
    }
}

__global__ void copy_grid_kernel(const float* __restrict__ x_grid,
                                 float* __restrict__ out) {
    const int i = blockIdx.x * blockDim.x + threadIdx.x;
    if (i < GG) out[i] = x_grid[i];
}

extern "C" void kernel_launch(void* const* d_in, const int* in_sizes, int n_in,
                              void* d_out, int out_size) {
    const float* xz     = (const float*)d_in[0];  // (B, N, 1)
    const float* z      = (const float*)d_in[1];  // (B, N, 1)
    const float* x_grid = (const float*)d_in[2];  // (G,)
    const float* ls     = (const float*)d_in[3];  // scalar
    const float* W      = (const float*)d_in[4];  // (3, C_OUT)
    const float* bias   = (const float*)d_in[5];  // (C_OUT,)

    float* out = (float*)d_out;

    // Reference returns (x_grid, out); if the harness output includes the
    // flattened x_grid first, write it and offset the main output.
    const long long main_sz = (long long)BB * CO * GG * GG;
    if ((long long)out_size >= main_sz + GG) {
        copy_grid_kernel<<<(GG + 255) / 256, 256>>>(x_grid, out);
        out += GG;
    }

    dim3 gridA(GG, BB);
    band_kernel<<<gridA, 96>>>(xz, z, x_grid, ls);

    dim3 gridB(1, GG, BB * CO);
    out_kernel<<<gridB, 128>>>(W, bias, out);
}

// round 2
// speedup vs baseline: 1.9385x; 1.9385x over previous
#include <cuda_runtime.h>

#define BB 2
#define NN 4096
#define GG 2048
#define CO 8
#define BW 32
#define BWIDTH (2 * BW + 1)       // 65
#define TILE 16
#define COLS (TILE + 2 * BW)      // 80
#define MAXP 224
#define CHUNK 64
#define NTHREADS 256
#define NOUT 5                    // ceil(16*65 / 256)

// Band scratch: 2 * 2 * 2048 * 65 * 4 B ~= 2.1 MB (stays in L2 for the fill pass)
__device__ float g_band0[BB][GG][BWIDTH];
__device__ float g_band1n[BB][GG][BWIDTH];

// ---------------------------------------------------------------------------
// Kernel A (tiled): one block per (b, 16-g tile).
//   band0[g][off]  = sum_n w[n,g] * w[n,g+off-BW]
//   band1n[g][off] = (sum_n z_n w[n,g] * w[n,h]) / (band0 + 1e-8)
// Points with max_g-in-tile w[n,g] < ~1e-18 are pruned (contribution below
// fp32 noise and far below the 1e-8 normalization floor).
// ---------------------------------------------------------------------------
__global__ __launch_bounds__(NTHREADS)
void band_kernel(const float* __restrict__ xz,
                 const float* __restrict__ z,
                 const float* __restrict__ x_grid,
                 const float* __restrict__ log_scale,
                 float* __restrict__ out_grid) {
    const int g0 = blockIdx.x * TILE;
    const int b = blockIdx.y;
    const int tid = threadIdx.x;
    const int wid = tid >> 5;
    const int lid = tid & 31;

    __shared__ float s_x[MAXP], s_z[MAXP];
    __shared__ float s_xg[COLS];
    __shared__ float s_w[CHUNK][COLS + 1];
    __shared__ int s_wcnt[8];
    __shared__ int s_cnt;

    const float inv = 0.5f / __expf(2.0f * log_scale[0]);   // = 50 here
    const float r = sqrtf(41.45f / inv);                    // exp(-41.45) ~ 1e-18

    // fused x_grid prefix copy (reference returns (x_grid, out))
    if (out_grid != nullptr && b == 0 && tid < TILE)
        out_grid[g0 + tid] = x_grid[g0 + tid];

    // stage grid coords for this tile's column window; sentinel for OOB
    if (tid < COLS) {
        const int gj = g0 - BW + tid;
        s_xg[tid] = (gj >= 0 && gj < GG) ? x_grid[gj] : 1e30f;
    }

    const float xlo = x_grid[g0] - r;
    const float xhi = x_grid[g0 + TILE - 1] + r;

    // ---- deterministic two-pass compaction: 8 warps, 512 points each ----
    const float* xb = xz + b * NN;
    const float* zb = z + b * NN;
    const int nstart = wid * (NN / 8);
    {
        int cnt = 0;
        for (int i = 0; i < NN / 8; i += 32) {
            const float x = xb[nstart + i + lid];
            const bool keep = (x >= xlo) && (x <= xhi);
            cnt += __popc(__ballot_sync(0xFFFFFFFFu, keep));
        }
        if (lid == 0) s_wcnt[wid] = cnt;
    }
    __syncthreads();
    {
        int offset = 0;
        for (int w = 0; w < wid; ++w) offset += s_wcnt[w];
        if (tid == 0) {
            int total = 0;
            for (int w = 0; w < 8; ++w) total += s_wcnt[w];
            s_cnt = (total < MAXP) ? total : MAXP;
        }
        const unsigned lanemask_lt = (1u << lid) - 1u;
        for (int i = 0; i < NN / 8; i += 32) {
            const int n = nstart + i + lid;
            const float x = xb[n];
            const bool keep = (x >= xlo) && (x <= xhi);
            const unsigned mask = __ballot_sync(0xFFFFFFFFu, keep);
            if (keep) {
                const int idx = offset + __popc(mask & lanemask_lt);
                if (idx < MAXP) {
                    s_x[idx] = x;
                    s_z[idx] = zb[n];
                }
            }
            offset += __popc(mask);
        }
    }
    __syncthreads();
    const int cnt = s_cnt;

    // ---- per-thread output assignment: outIdx = gl*65 + off ----
    int jg[NOUT], jh[NOUT];
    float a0[NOUT], a1[NOUT];
#pragma unroll
    for (int o = 0; o < NOUT; ++o) {
        const int outIdx = tid + o * NTHREADS;
        a0[o] = 0.0f;
        a1[o] = 0.0f;
        if (outIdx < TILE * BWIDTH) {
            const int gl = outIdx / BWIDTH;
            const int off = outIdx - gl * BWIDTH;
            jg[o] = gl + BW;
            jh[o] = gl + off;
        } else {
            jg[o] = 0;
            jh[o] = 0;
        }
    }

    // ---- chunked shared-w GEMM ----
    for (int base = 0; base < cnt; base += CHUNK) {
        const int m = min(CHUNK, cnt - base);
        __syncthreads();   // protect s_w reuse across iterations
        for (int idx = tid; idx < m * COLS; idx += NTHREADS) {
            const int p = idx / COLS;
            const int j = idx - p * COLS;
            const float d = s_x[base + p] - s_xg[j];
            s_w[p][j] = __expf(-inv * d * d);
        }
        __syncthreads();
        for (int i = 0; i < m; ++i) {
            const float zi = s_z[base + i];
#pragma unroll
            for (int o = 0; o < NOUT; ++o) {
                const float t = s_w[i][jg[o]] * s_w[i][jh[o]];
                a0[o] += t;
                a1[o] = fmaf(zi, t, a1[o]);
            }
        }
    }

#pragma unroll
    for (int o = 0; o < NOUT; ++o) {
        const int outIdx = tid + o * NTHREADS;
        if (outIdx < TILE * BWIDTH) {
            const int gl = outIdx / BWIDTH;
            const int off = outIdx - gl * BWIDTH;
            g_band0[b][g0 + gl][off] = a0[o];
            g_band1n[b][g0 + gl][off] = a1[o] / (a0[o] + 1e-8f);
        }
    }
}

// ---------------------------------------------------------------------------
// Kernel B: full (B, C_OUT, G, G) output; one 512-thread block per row,
// one float4 streaming store per thread.
//   out[b,o,g,h] = bias[o] + W[0,o]*(g==h) + W[1,o]*band0 + W[2,o]*band1n
// ---------------------------------------------------------------------------
__global__ __launch_bounds__(512)
void out_kernel(const float* __restrict__ W,
                const float* __restrict__ bias,
                float* __restrict__ out) {
    const int g = blockIdx.x;
    const int bo = blockIdx.y;           // b * CO + o
    const int b = bo >> 3;
    const int o = bo & 7;

    const float W0 = W[o];
    const float W1 = W[CO + o];
    const float W2 = W[2 * CO + o];
    const float bb = bias[o];

    const float* __restrict__ bd0 = g_band0[b][g];
    const float* __restrict__ bd1 = g_band1n[b][g];

    float4* row = reinterpret_cast<float4*>(out + ((size_t)bo * GG + g) * GG);
    const int h0 = threadIdx.x * 4;
    const int lo = g - BW;

    float4 v = make_float4(bb, bb, bb, bb);
    if (h0 + 3 >= lo && h0 <= g + BW) {
        float* vp = &v.x;
#pragma unroll
        for (int j = 0; j < 4; ++j) {
            const int off = h0 + j - lo;
            if (off >= 0 && off < BWIDTH) {
                float val = bb + W1 * bd0[off] + W2 * bd1[off];
                if (h0 + j == g) val += W0;
                vp[j] = val;
            }
        }
    }
    __stcs(&row[threadIdx.x], v);
}

extern "C" void kernel_launch(void* const* d_in, const int* in_sizes, int n_in,
                              void* d_out, int out_size) {
    const float* xz     = (const float*)d_in[0];  // (B, N, 1)
    const float* z      = (const float*)d_in[1];  // (B, N, 1)
    const float* x_grid = (const float*)d_in[2];  // (G,)
    const float* ls     = (const float*)d_in[3];  // scalar
    const float* W      = (const float*)d_in[4];  // (3, C_OUT)
    const float* bias   = (const float*)d_in[5];  // (C_OUT,)

    float* out = (float*)d_out;
    float* grid_prefix = nullptr;

    const long long main_sz = (long long)BB * CO * GG * GG;
    if ((long long)out_size >= main_sz + GG) {
        grid_prefix = out;
        out += GG;
    }

    dim3 gridA(GG / TILE, BB);
    band_kernel<<<gridA, NTHREADS>>>(xz, z, x_grid, ls, grid_prefix);

    dim3 gridB(GG, BB * CO);
    out_kernel<<<gridB, 512>>>(W, bias, out);
}